// round 13
// baseline (speedup 1.0000x reference)
#include <cuda_runtime.h>
#include <math.h>

typedef unsigned long long ULL;

// ---------------- scratch ----------------
__device__ float g_x1[512*32*30*30];     // conv1 out
__device__ float g_x2[512*64*14*14];     // conv2 out
__device__ float g_x3[512*32*12*12];     // conv3 out == fc input rows [512][4608]
__device__ float g_fc[512*512];          // fc out
__device__ float g_gi[512*1536];         // input-to-hidden gates
__device__ float g_h[16*512];            // GRU hidden
__device__ float g_outs[512*512];        // GRU outputs per (t,n)
__device__ float g_red[16*512*512];      // split-K partials
__device__ int   g_bar;                  // GRU grid barrier counter

// ---------------- f32x2 helpers ----------------
__device__ __forceinline__ ULL ffma2(ULL a, ULL b, ULL c) {
    ULL d;
    asm("fma.rn.f32x2 %0, %1, %2, %3;" : "=l"(d) : "l"(a), "l"(b), "l"(c));
    return d;
}
__device__ __forceinline__ ULL add2(ULL a, ULL b) {
    ULL d;
    asm("add.rn.f32x2 %0, %1, %2;" : "=l"(d) : "l"(a), "l"(b));
    return d;
}
__device__ __forceinline__ float2 unpack2(ULL a) {
    float2 u;
    asm("mov.b64 {%0, %1}, %2;" : "=f"(u.x), "=f"(u.y) : "l"(a));
    return u;
}
__device__ __forceinline__ ULL dup2(float x) {
    ULL r;
    asm("mov.b64 %0, {%1, %1};" : "=l"(r) : "f"(x));
    return r;
}

// 8 oc-pairs x 2 spatial
#define FMA16(wa,wb,wc,wd,d0,d1,A) do { \
    A[0][0]=ffma2(wa.x,d0,A[0][0]); A[0][1]=ffma2(wa.x,d1,A[0][1]); \
    A[1][0]=ffma2(wa.y,d0,A[1][0]); A[1][1]=ffma2(wa.y,d1,A[1][1]); \
    A[2][0]=ffma2(wb.x,d0,A[2][0]); A[2][1]=ffma2(wb.x,d1,A[2][1]); \
    A[3][0]=ffma2(wb.y,d0,A[3][0]); A[3][1]=ffma2(wb.y,d1,A[3][1]); \
    A[4][0]=ffma2(wc.x,d0,A[4][0]); A[4][1]=ffma2(wc.x,d1,A[4][1]); \
    A[5][0]=ffma2(wc.y,d0,A[5][0]); A[5][1]=ffma2(wc.y,d1,A[5][1]); \
    A[6][0]=ffma2(wd.x,d0,A[6][0]); A[6][1]=ffma2(wd.x,d1,A[6][1]); \
    A[7][0]=ffma2(wd.y,d0,A[7][0]); A[7][1]=ffma2(wd.y,d1,A[7][1]); } while(0)

__global__ void k_dummy() {}

// ---------------- conv1: [512,4,124,124] -> [512,32,30,30], 8x8 s4 ----------------
// 512 thr = 2 ksplit(ic pairs) x 2 och(16 oc) x 128(120 spatial). 4 oy passes.
__global__ void k_conv1(const float* __restrict__ in, const float* __restrict__ w,
                        const float* __restrict__ bias) {
    extern __shared__ float s1[];
    float* sW = s1;            // [k 256][oc pad 36] = 9216
    float* sI = s1 + 9216;     // [ic 4][y 36][x 124] = 17856 (reused as reduce buf)
    int n = blockIdx.x, tid = threadIdx.x;
    for (int i = tid; i < 8192; i += 512) {
        int oc = i >> 8, k = i & 255;
        sW[k*36 + oc] = w[i];
    }
    int ks = tid >> 8, r = tid & 255;
    int och = r >> 7, rem = r & 127;
    bool act = rem < 120;
    int oyL = act ? rem/15 : 0, oxp = act ? rem%15 : 0;
    const float* inN = in + (size_t)n*61504;
    const float inv255 = 1.f/255.f;
    for (int p = 0; p < 4; p++) {
        int y0 = 32*p;
        int ylim = 124 - y0; if (ylim > 36) ylim = 36;
        __syncthreads();
        for (int i = tid; i < 17856; i += 512) {
            int ic = i / 4464, r2 = i - ic*4464;
            int y = r2 / 124, x = r2 - y*124;
            if (y < ylim) sI[i] = inN[ic*15376 + (y0+y)*124 + x];
        }
        __syncthreads();
        ULL acc[8][2];
        #pragma unroll
        for (int j = 0; j < 8; j++) { acc[j][0] = 0ULL; acc[j][1] = 0ULL; }
        #pragma unroll 1
        for (int ic = ks*2; ic < ks*2 + 2; ic++) {
            #pragma unroll
            for (int ky = 0; ky < 8; ky++) {
                const float4* ip = (const float4*)&sI[ic*4464 + (4*oyL+ky)*124 + 8*oxp];
                float4 i0 = ip[0], i1 = ip[1], i2 = ip[2];
                float inr[12] = {i0.x,i0.y,i0.z,i0.w, i1.x,i1.y,i1.z,i1.w, i2.x,i2.y,i2.z,i2.w};
                #pragma unroll
                for (int kx = 0; kx < 8; kx++) {
                    int k = ic*64 + ky*8 + kx;
                    const ulonglong2* wp = (const ulonglong2*)&sW[k*36 + och*16];
                    ulonglong2 wa = wp[0], wb = wp[1], wc = wp[2], wd = wp[3];
                    ULL d0 = dup2(inr[kx]), d1 = dup2(inr[kx+4]);
                    FMA16(wa, wb, wc, wd, d0, d1, acc);
                }
            }
        }
        __syncthreads();                 // compute done; sI now dead
        ULL* buf = (ULL*)sI;             // 256*16 ULL = 32768 B < 71424 B
        if (ks == 1) {
            #pragma unroll
            for (int j = 0; j < 8; j++) {
                buf[r*16 + 2*j]     = acc[j][0];
                buf[r*16 + 2*j + 1] = acc[j][1];
            }
        }
        __syncthreads();
        int oy = 8*p + oyL;
        if (ks == 0 && act && oy < 30) {
            float* op = g_x1 + (size_t)n*28800 + oy*30 + 2*oxp;
            #pragma unroll
            for (int j = 0; j < 8; j++) {
                ULL s0 = add2(acc[j][0], buf[r*16 + 2*j]);
                ULL s1 = add2(acc[j][1], buf[r*16 + 2*j + 1]);
                int oc = och*16 + 2*j;
                float2 a0 = unpack2(s0), a1 = unpack2(s1);
                float b0 = bias[oc], b1 = bias[oc+1];
                float2 v0 = make_float2(fmaxf(a0.x*inv255 + b0, 0.f), fmaxf(a1.x*inv255 + b0, 0.f));
                float2 v1 = make_float2(fmaxf(a0.y*inv255 + b1, 0.f), fmaxf(a1.y*inv255 + b1, 0.f));
                *(float2*)&op[(size_t)oc*900]     = v0;
                *(float2*)&op[(size_t)(oc+1)*900] = v1;
            }
        }
    }
}

// ---------------- conv2: [512,32,30,30] -> [512,64,14,14], 4x4 s2 ----------------
// grid (512, 2). 448 thr = 2 ksplit x 2 ocg(16 oc) x 112 spatial. in-block ic-split.
__global__ __launch_bounds__(448, 1)
void k_conv2(const float* __restrict__ w, const float* __restrict__ bias) {
    extern __shared__ float s2[];
    float* sW = s2;            // [k 512][oc pad 36] = 18432
    float* sI = s2 + 18432;    // [ic 32][y 30][x pad 32] = 30720
    int n = blockIdx.x, h = blockIdx.y, tid = threadIdx.x;
    for (int i = tid; i < 16384; i += 448) {
        int oc = i >> 9, k = i & 511;
        sW[k*36 + oc] = w[(h*32+oc)*512 + k];
    }
    const float* src = g_x1 + (size_t)n*28800;
    for (int i = tid; i < 28800; i += 448) {
        int ic = i / 900, r = i - ic*900;
        int y = r / 30, x = r - y*30;
        sI[ic*960 + y*32 + x] = src[i];
    }
    __syncthreads();
    int ks = tid / 224, r = tid - ks*224;
    int ocg = r / 112, idx = r - ocg*112;
    bool act = idx < 98;
    int oy = act ? idx/7 : 0, oxp = act ? idx%7 : 0;
    ULL acc[8][2];
    #pragma unroll
    for (int j = 0; j < 8; j++) { acc[j][0] = 0ULL; acc[j][1] = 0ULL; }
    #pragma unroll 1
    for (int ic = ks*16; ic < ks*16 + 16; ic++) {
        #pragma unroll
        for (int ky = 0; ky < 4; ky++) {
            const float4* ip = (const float4*)&sI[ic*960 + (2*oy+ky)*32 + 4*oxp];
            float4 i0 = ip[0], i1 = ip[1];
            float inr[8] = {i0.x,i0.y,i0.z,i0.w, i1.x,i1.y,i1.z,i1.w};
            #pragma unroll
            for (int kx = 0; kx < 4; kx++) {
                int k = ic*16 + ky*4 + kx;
                const ulonglong2* wp = (const ulonglong2*)&sW[k*36 + ocg*16];
                ulonglong2 wa = wp[0], wb = wp[1], wc = wp[2], wd = wp[3];
                ULL d0 = dup2(inr[kx]), d1 = dup2(inr[kx+2]);
                FMA16(wa, wb, wc, wd, d0, d1, acc);
            }
        }
    }
    __syncthreads();
    ULL* buf = (ULL*)sW;                 // 224*16 ULL = 28672 B < 73728 B
    if (ks == 1) {
        #pragma unroll
        for (int j = 0; j < 8; j++) {
            buf[r*16 + 2*j]     = acc[j][0];
            buf[r*16 + 2*j + 1] = acc[j][1];
        }
    }
    __syncthreads();
    if (ks == 0 && act) {
        float* op = g_x2 + (size_t)(n*64 + h*32)*196 + oy*14 + 2*oxp;
        #pragma unroll
        for (int j = 0; j < 8; j++) {
            ULL s0 = add2(acc[j][0], buf[r*16 + 2*j]);
            ULL s1 = add2(acc[j][1], buf[r*16 + 2*j + 1]);
            int oc = ocg*16 + 2*j;
            float2 a0 = unpack2(s0), a1 = unpack2(s1);
            float b0 = bias[h*32 + oc], b1 = bias[h*32 + oc + 1];
            float2 v0 = make_float2(fmaxf(a0.x + b0, 0.f), fmaxf(a1.x + b0, 0.f));
            float2 v1 = make_float2(fmaxf(a0.y + b1, 0.f), fmaxf(a1.y + b1, 0.f));
            *(float2*)&op[(size_t)oc*196]     = v0;
            *(float2*)&op[(size_t)(oc+1)*196] = v1;
        }
    }
}

// ---------------- conv3: [512,64,14,14] -> [512,32,12,12], 3x3 s1 ----------------
// grid 256 (2 imgs/block). 576 thr = 2 ksplit x (2 img x 2 ocg(16 oc) x 72 spatial).
__global__ __launch_bounds__(576, 1)
void k_conv3(const float* __restrict__ w, const float* __restrict__ bias) {
    extern __shared__ float s3[];
    float* sW = s3;            // [k 576][oc pad 36] = 20736
    float* sI = s3 + 20736;    // [img 2][ic 64][y 14][x pad 16] = 28672
    int n0 = blockIdx.x*2, tid = threadIdx.x;
    for (int i = tid; i < 18432; i += 576) {
        int oc = i / 576, k = i - oc*576;
        sW[k*36 + oc] = w[i];
    }
    for (int i = tid; i < 25088; i += 576) {
        int img = i / 12544, r = i - img*12544;
        int ic = r / 196, r2 = r - ic*196;
        int y = r2 / 14, x = r2 - y*14;
        sI[img*14336 + ic*224 + y*16 + x] = g_x2[(size_t)(n0+img)*12544 + r];
    }
    __syncthreads();
    int ks = tid / 288, r = tid - ks*288;
    int img = r / 144, rr = r - img*144;
    int ocg = rr / 72, sp = rr - ocg*72;
    int oy = sp / 6, oxp = sp - oy*6;
    int x0 = 2*oxp, al = x0 & ~3, o = x0 & 3;
    ULL acc[8][2];
    #pragma unroll
    for (int j = 0; j < 8; j++) { acc[j][0] = 0ULL; acc[j][1] = 0ULL; }
    const float* base = sI + img*14336;
    #pragma unroll 1
    for (int ic = ks*32; ic < ks*32 + 32; ic++) {
        #pragma unroll
        for (int ky = 0; ky < 3; ky++) {
            const float4* ip = (const float4*)&base[ic*224 + (oy+ky)*16 + al];
            float4 i0 = ip[0], i1 = ip[1];
            float inr[8] = {i0.x,i0.y,i0.z,i0.w, i1.x,i1.y,i1.z,i1.w};
            #pragma unroll
            for (int kx = 0; kx < 3; kx++) {
                int k = ic*9 + ky*3 + kx;
                const ulonglong2* wp = (const ulonglong2*)&sW[k*36 + ocg*16];
                ulonglong2 wa = wp[0], wb = wp[1], wc = wp[2], wd = wp[3];
                ULL d0 = dup2(inr[o+kx]), d1 = dup2(inr[o+1+kx]);
                FMA16(wa, wb, wc, wd, d0, d1, acc);
            }
        }
    }
    __syncthreads();
    ULL* buf = (ULL*)sW;                 // 288*16 ULL = 36864 B < 82944 B
    if (ks == 1) {
        #pragma unroll
        for (int j = 0; j < 8; j++) {
            buf[r*16 + 2*j]     = acc[j][0];
            buf[r*16 + 2*j + 1] = acc[j][1];
        }
    }
    __syncthreads();
    if (ks == 0) {
        float* op = g_x3 + (size_t)(n0+img)*4608 + oy*12 + 2*oxp;
        #pragma unroll
        for (int j = 0; j < 8; j++) {
            ULL s0 = add2(acc[j][0], buf[r*16 + 2*j]);
            ULL s1 = add2(acc[j][1], buf[r*16 + 2*j + 1]);
            int oc = ocg*16 + 2*j;
            float2 a0 = unpack2(s0), a1 = unpack2(s1);
            float b0 = bias[oc], b1 = bias[oc+1];
            float2 v0 = make_float2(fmaxf(a0.x + b0, 0.f), fmaxf(a1.x + b0, 0.f));
            float2 v1 = make_float2(fmaxf(a0.y + b1, 0.f), fmaxf(a1.y + b1, 0.f));
            *(float2*)&op[(size_t)oc*144]     = v0;
            *(float2*)&op[(size_t)(oc+1)*144] = v1;
        }
    }
}

// ---------------- split-K f32x2 GEMM v3 ----------------
template<int N, int K, int S>
__global__ void k_gemm3(const float* __restrict__ A, const float* __restrict__ Bm,
                        float* __restrict__ Cp) {
    const int KS = K / S;
    __shared__ __align__(16) float As[16*128];   // [k][m] m-transposed
    __shared__ __align__(16) float Bs[16*128];   // [k][n] natural
    int tid = threadIdx.x;
    int tx = tid & 15, ty = tid >> 4;
    int n0 = blockIdx.x*128, m0 = blockIdx.y*128, ks = blockIdx.z;
    int kbase = ks*KS;
    const int MN = gridDim.y*128*N;

    ULL acc[4][8];
    #pragma unroll
    for (int i = 0; i < 4; i++)
        #pragma unroll
        for (int j = 0; j < 8; j++) acc[i][j] = 0ULL;

    int mA = tid & 127, cA = tid >> 7;

    for (int k0 = kbase; k0 < kbase + KS; k0 += 16) {
        __syncthreads();
        #pragma unroll
        for (int u = 0; u < 2; u++) {
            int c = cA + 2*u;
            float4 v = *(const float4*)&A[(size_t)(m0+mA)*K + k0 + 4*c];
            As[(4*c+0)*128 + mA] = v.x;
            As[(4*c+1)*128 + mA] = v.y;
            As[(4*c+2)*128 + mA] = v.z;
            As[(4*c+3)*128 + mA] = v.w;
        }
        #pragma unroll
        for (int u = 0; u < 2; u++) {
            int c = cA + 2*u;
            float4 v = *(const float4*)&Bm[(size_t)(n0+mA)*K + k0 + 4*c];
            Bs[(4*c+0)*128 + mA] = v.x;
            Bs[(4*c+1)*128 + mA] = v.y;
            Bs[(4*c+2)*128 + mA] = v.z;
            Bs[(4*c+3)*128 + mA] = v.w;
        }
        __syncthreads();
        #pragma unroll
        for (int kk = 0; kk < 16; kk++) {
            ulonglong2 aA = *(const ulonglong2*)&As[kk*128 + 8*ty];
            ulonglong2 aB = *(const ulonglong2*)&As[kk*128 + 8*ty + 4];
            float4 b0 = *(const float4*)&Bs[kk*128 + 4*tx];
            float4 b1 = *(const float4*)&Bs[kk*128 + 64 + 4*tx];
            ULL a[4] = {aA.x, aA.y, aB.x, aB.y};
            ULL bd[8] = {dup2(b0.x), dup2(b0.y), dup2(b0.z), dup2(b0.w),
                         dup2(b1.x), dup2(b1.y), dup2(b1.z), dup2(b1.w)};
            #pragma unroll
            for (int i = 0; i < 4; i++)
                #pragma unroll
                for (int j = 0; j < 8; j++)
                    acc[i][j] = ffma2(a[i], bd[j], acc[i][j]);
        }
    }
    float* cp = Cp + (size_t)ks*MN;
    #pragma unroll
    for (int i = 0; i < 4; i++) {
        int m = m0 + 8*ty + 2*i;
        #pragma unroll
        for (int j = 0; j < 8; j++) {
            int nn = n0 + (j < 4 ? 4*tx + j : 64 + 4*tx + (j-4));
            float2 v = unpack2(acc[i][j]);
            cp[(size_t)m*N + nn]     = v.x;
            cp[(size_t)(m+1)*N + nn] = v.y;
        }
    }
}

template<int S, int NC, bool RELU>
__global__ void k_red(const float* __restrict__ bias, float* __restrict__ C, int MN) {
    int i = blockIdx.x*256 + threadIdx.x;
    if (i >= MN) return;
    float s = bias[i % NC];
    #pragma unroll
    for (int j = 0; j < S; j++) s += g_red[(size_t)j*MN + i];
    C[i] = RELU ? fmaxf(s, 0.f) : s;
}

// ---------------- GRU: persistent, 64 blocks, k-split 2 per thread ----------------
__global__ void k_init_h(const float* __restrict__ states) {
    int i = blockIdx.x*256 + threadIdx.x;   // < 8192
    g_h[i] = states[i];
    if (i == 0) g_bar = 0;
}

__global__ void k_gru(const float* __restrict__ w_hh, const float* __restrict__ masks,
                      const float* __restrict__ b_hh) {
    extern __shared__ float sm[];
    float* w_s = sm;                 // 24*512 = 12288
    float* h_s = sm + 12288;         // 16*514 = 8224
    int tid = threadIdx.x, b = blockIdx.x;
    int hh0 = b*8;
    for (int idx = tid; idx < 12288; idx += 256) {
        int lr = idx >> 9, k = idx & 511;
        int grow = (lr >> 3)*512 + hh0 + (lr & 7);
        w_s[idx] = w_hh[(size_t)grow*512 + k];
    }
    int hh_l = tid >> 5, n = (tid >> 1) & 15, ks = tid & 1;
    int hh = hh0 + hh_l;
    float br = b_hh[hh], bz = b_hh[512+hh], bn = b_hh[1024+hh];
    const float* wr = w_s + hh_l*512 + ks*256;
    const float* wz = w_s + (8+hh_l)*512 + ks*256;
    const float* wn = w_s + (16+hh_l)*512 + ks*256;
    const float* hp = h_s + n*514 + ks*256;

    for (int t = 0; t < 32; t++) {
        int row = t*16 + n;
        float gi_r = g_gi[(size_t)row*1536 + hh];
        float gi_z = g_gi[(size_t)row*1536 + 512 + hh];
        float gi_n = g_gi[(size_t)row*1536 + 1024 + hh];
        for (int idx = tid; idx < 8192; idx += 256) {
            int nn = idx >> 9, k = idx & 511;
            h_s[nn*514 + k] = g_h[idx] * masks[t*16 + nn];
        }
        __syncthreads();

        ULL ar0=0,ar1=0, az0=0,az1=0, an0=0,an1=0;
        #pragma unroll 8
        for (int k = 0; k < 256; k += 8) {
            ULL h0 = *(const ULL*)(hp+k);
            ULL h1 = *(const ULL*)(hp+k+2);
            ULL h2 = *(const ULL*)(hp+k+4), h3 = *(const ULL*)(hp+k+6);
            ulonglong2 ra = *(const ulonglong2*)(wr+k), rb = *(const ulonglong2*)(wr+k+4);
            ulonglong2 za = *(const ulonglong2*)(wz+k), zb = *(const ulonglong2*)(wz+k+4);
            ulonglong2 na = *(const ulonglong2*)(wn+k), nb = *(const ulonglong2*)(wn+k+4);
            ar0 = ffma2(ra.x, h0, ar0); ar1 = ffma2(ra.y, h1, ar1);
            az0 = ffma2(za.x, h0, az0); az1 = ffma2(za.y, h1, az1);
            an0 = ffma2(na.x, h0, an0); an1 = ffma2(na.y, h1, an1);
            ar0 = ffma2(rb.x, h2, ar0); ar1 = ffma2(rb.y, h3, ar1);
            az0 = ffma2(zb.x, h2, az0); az1 = ffma2(zb.y, h3, az1);
            an0 = ffma2(nb.x, h2, an0); an1 = ffma2(nb.y, h3, an1);
        }
        float2 u0 = unpack2(ar0), u1 = unpack2(ar1);
        float sr = u0.x + u0.y + u1.x + u1.y;
        u0 = unpack2(az0); u1 = unpack2(az1);
        float sz = u0.x + u0.y + u1.x + u1.y;
        u0 = unpack2(an0); u1 = unpack2(an1);
        float sn = u0.x + u0.y + u1.x + u1.y;
        sr += __shfl_xor_sync(0xffffffffu, sr, 1);
        sz += __shfl_xor_sync(0xffffffffu, sz, 1);
        sn += __shfl_xor_sync(0xffffffffu, sn, 1);
        sr += br; sz += bz; sn += bn;

        float rg = 1.f/(1.f + expf(-(gi_r + sr)));
        float zg = 1.f/(1.f + expf(-(gi_z + sz)));
        float ng = tanhf(gi_n + rg*sn);
        float hm = h_s[n*514 + hh];
        float hnew = (1.f - zg)*ng + zg*hm;
        if (ks == 0) {
            g_h[n*512 + hh] = hnew;
            g_outs[(size_t)row*512 + hh] = hnew;
        }

        __threadfence();
        __syncthreads();
        if (tid == 0) {
            atomicAdd(&g_bar, 1);
            while (atomicAdd(&g_bar, 0) < 64*(t+1)) { }
        }
        __syncthreads();
    }
}

// ---------------- heads ----------------
__global__ void k_heads(const float* __restrict__ aw, const float* __restrict__ ab,
                        const float* __restrict__ cw, const float* __restrict__ cb,
                        const int* __restrict__ action, float* __restrict__ out) {
    int wrp = threadIdx.x >> 5, lane = threadIdx.x & 31;
    int row = blockIdx.x*4 + wrp;
    const float* x = g_outs + (size_t)row*512;
    float p[7];
    #pragma unroll
    for (int j = 0; j < 7; j++) p[j] = 0.f;
    for (int k = lane; k < 512; k += 32) {
        float xv = x[k];
        #pragma unroll
        for (int j = 0; j < 6; j++) p[j] += xv * aw[j*512 + k];
        p[6] += xv * cw[k];
    }
    #pragma unroll
    for (int j = 0; j < 7; j++)
        #pragma unroll
        for (int o = 16; o > 0; o >>= 1) p[j] += __shfl_xor_sync(0xffffffffu, p[j], o);
    if (lane == 0) {
        float l[6];
        #pragma unroll
        for (int j = 0; j < 6; j++) l[j] = p[j] + ab[j];
        float v = p[6] + cb[0];
        float m = l[0];
        #pragma unroll
        for (int j = 1; j < 6; j++) m = fmaxf(m, l[j]);
        float se = 0.f;
        #pragma unroll
        for (int j = 0; j < 6; j++) se += expf(l[j] - m);
        float lse = m + logf(se);
        int a = action[row];
        float alp = 0.f;
        #pragma unroll
        for (int j = 0; j < 6; j++) if (j == a) alp = l[j] - lse;
        float ent = 0.f;
        #pragma unroll
        for (int j = 0; j < 6; j++) { float lp = l[j] - lse; ent -= expf(lp)*lp; }
        out[row] = v;
        out[512 + row] = alp;
        out[1024 + row] = ent;
    }
}

__global__ void k_states_out(float* __restrict__ out) {
    int i = blockIdx.x*256 + threadIdx.x;   // < 8192
    out[1536 + i] = g_h[i];
}

// ---------------- launch ----------------
extern "C" void kernel_launch(void* const* d_in, const int* in_sizes, int n_in,
                              void* d_out, int out_size) {
    const float* inputs   = (const float*)d_in[0];
    const float* states   = (const float*)d_in[1];
    const float* masks    = (const float*)d_in[2];
    const int*   action   = (const int*)d_in[3];
    const float* conv1_w  = (const float*)d_in[4];
    const float* conv1_b  = (const float*)d_in[5];
    const float* conv2_w  = (const float*)d_in[6];
    const float* conv2_b  = (const float*)d_in[7];
    const float* conv3_w  = (const float*)d_in[8];
    const float* conv3_b  = (const float*)d_in[9];
    const float* fc_w     = (const float*)d_in[10];
    const float* fc_b     = (const float*)d_in[11];
    const float* w_ih     = (const float*)d_in[12];
    const float* w_hh     = (const float*)d_in[13];
    const float* b_ih     = (const float*)d_in[14];
    const float* b_hh     = (const float*)d_in[15];
    const float* actor_w  = (const float*)d_in[16];
    const float* actor_b  = (const float*)d_in[17];
    const float* critic_w = (const float*)d_in[18];
    const float* critic_b = (const float*)d_in[19];
    float* out = (float*)d_out;
    (void)in_sizes; (void)n_in; (void)out_size;

    float* d_red;  cudaGetSymbolAddress((void**)&d_red, g_red);
    float* d_x3;   cudaGetSymbolAddress((void**)&d_x3, g_x3);
    float* d_fc;   cudaGetSymbolAddress((void**)&d_fc, g_fc);
    float* d_gi;   cudaGetSymbolAddress((void**)&d_gi, g_gi);

    cudaFuncSetAttribute(k_conv1, cudaFuncAttributeMaxDynamicSharedMemorySize, 108288);
    cudaFuncSetAttribute(k_conv2, cudaFuncAttributeMaxDynamicSharedMemorySize, 196608);
    cudaFuncSetAttribute(k_conv3, cudaFuncAttributeMaxDynamicSharedMemorySize, 197632);
    cudaFuncSetAttribute(k_gru,   cudaFuncAttributeMaxDynamicSharedMemorySize, 82048);

    // launches #1-#3 put the ncu capture slot (#4) on k_conv1
    k_init_h<<<32, 256>>>(states);
    k_dummy<<<1, 32>>>();
    k_dummy<<<1, 32>>>();

    k_conv1<<<512, 512, 108288>>>(inputs, conv1_w, conv1_b);
    k_conv2<<<dim3(512, 2), 448, 196608>>>(conv2_w, conv2_b);
    k_conv3<<<256, 576, 197632>>>(conv3_w, conv3_b);

    // fc: M=512, N=512, K=4608, split 16 -> 256 blocks
    k_gemm3<512, 4608, 16><<<dim3(4, 4, 16), 256>>>(d_x3, fc_w, d_red);
    k_red<16, 512, true><<<1024, 256>>>(fc_b, d_fc, 512*512);
    // gi: M=512, N=1536, K=512, split 4 -> 192 blocks
    k_gemm3<1536, 512, 4><<<dim3(12, 4, 4), 256>>>(d_fc, w_ih, d_red);
    k_red<4, 1536, false><<<3072, 256>>>(b_ih, d_gi, 512*1536);

    k_gru<<<64, 256, 82048>>>(w_hh, masks, b_hh);

    k_heads<<<128, 128>>>(actor_w, actor_b, critic_w, critic_b, action, out);
    k_states_out<<<32, 256>>>(out);
}

// round 14
// speedup vs baseline: 1.0574x; 1.0574x over previous
#include <cuda_runtime.h>
#include <math.h>

typedef unsigned long long ULL;

// ---------------- scratch ----------------
__device__ float g_x1[512*32*30*30];     // conv1 out
__device__ float g_x2[512*64*14*14];     // conv2 out
__device__ float g_x3[512*32*12*12];     // conv3 out == fc input rows [512][4608]
__device__ float g_fc[512*512];          // fc out
__device__ float g_gi[512*1536];         // input-to-hidden gates
__device__ float g_h[16*512];            // GRU hidden
__device__ float g_outs[512*512];        // GRU outputs per (t,n)
__device__ float g_red[16*512*512];      // split-K partials
__device__ int   g_bar;                  // GRU grid barrier counter

// ---------------- f32x2 helpers ----------------
__device__ __forceinline__ ULL ffma2(ULL a, ULL b, ULL c) {
    ULL d;
    asm("fma.rn.f32x2 %0, %1, %2, %3;" : "=l"(d) : "l"(a), "l"(b), "l"(c));
    return d;
}
__device__ __forceinline__ ULL add2(ULL a, ULL b) {
    ULL d;
    asm("add.rn.f32x2 %0, %1, %2;" : "=l"(d) : "l"(a), "l"(b));
    return d;
}
__device__ __forceinline__ float2 unpack2(ULL a) {
    float2 u;
    asm("mov.b64 {%0, %1}, %2;" : "=f"(u.x), "=f"(u.y) : "l"(a));
    return u;
}
__device__ __forceinline__ ULL dup2(float x) {
    ULL r;
    asm("mov.b64 %0, {%1, %1};" : "=l"(r) : "f"(x));
    return r;
}

// 4 oc-pairs x 2 spatial
#define FMA8(wa,wb,d0,d1,A) do { \
    A[0][0]=ffma2(wa.x,d0,A[0][0]); A[0][1]=ffma2(wa.x,d1,A[0][1]); \
    A[1][0]=ffma2(wa.y,d0,A[1][0]); A[1][1]=ffma2(wa.y,d1,A[1][1]); \
    A[2][0]=ffma2(wb.x,d0,A[2][0]); A[2][1]=ffma2(wb.x,d1,A[2][1]); \
    A[3][0]=ffma2(wb.y,d0,A[3][0]); A[3][1]=ffma2(wb.y,d1,A[3][1]); } while(0)

// 8 oc-pairs x 2 spatial
#define FMA16(wa,wb,wc,wd,d0,d1,A) do { \
    A[0][0]=ffma2(wa.x,d0,A[0][0]); A[0][1]=ffma2(wa.x,d1,A[0][1]); \
    A[1][0]=ffma2(wa.y,d0,A[1][0]); A[1][1]=ffma2(wa.y,d1,A[1][1]); \
    A[2][0]=ffma2(wb.x,d0,A[2][0]); A[2][1]=ffma2(wb.x,d1,A[2][1]); \
    A[3][0]=ffma2(wb.y,d0,A[3][0]); A[3][1]=ffma2(wb.y,d1,A[3][1]); \
    A[4][0]=ffma2(wc.x,d0,A[4][0]); A[4][1]=ffma2(wc.x,d1,A[4][1]); \
    A[5][0]=ffma2(wc.y,d0,A[5][0]); A[5][1]=ffma2(wc.y,d1,A[5][1]); \
    A[6][0]=ffma2(wd.x,d0,A[6][0]); A[6][1]=ffma2(wd.x,d1,A[6][1]); \
    A[7][0]=ffma2(wd.y,d0,A[7][0]); A[7][1]=ffma2(wd.y,d1,A[7][1]); } while(0)

// ---------------- conv1: [512,4,124,124] -> [512,32,30,30], 8x8 s4 (R12 FMA8) ----------------
__global__ __launch_bounds__(512, 2)
void k_conv1(const float* __restrict__ in, const float* __restrict__ w,
             const float* __restrict__ bias) {
    extern __shared__ float s1[];
    float* sW = s1;            // [k 256][oc pad 36] = 9216
    float* sI = s1 + 9216;     // [ic 4][y 36][x 124] = 17856
    int n = blockIdx.x, tid = threadIdx.x;
    for (int i = tid; i < 8192; i += 512) {
        int oc = i >> 8, k = i & 255;
        sW[k*36 + oc] = w[i];
    }
    int och = tid >> 7, rem = tid & 127;
    bool act = rem < 120;
    int oyL = act ? rem/15 : 0, oxp = act ? rem%15 : 0;
    const float* inN = in + (size_t)n*61504;
    const float inv255 = 1.f/255.f;
    for (int p = 0; p < 4; p++) {
        int y0 = 32*p;
        int ylim = 124 - y0; if (ylim > 36) ylim = 36;
        __syncthreads();
        for (int i = tid; i < 17856; i += 512) {
            int ic = i / 4464, r2 = i - ic*4464;
            int y = r2 / 124, x = r2 - y*124;
            if (y < ylim) sI[i] = inN[ic*15376 + (y0+y)*124 + x];
        }
        __syncthreads();
        ULL acc[4][2];
        #pragma unroll
        for (int j = 0; j < 4; j++) { acc[j][0] = 0ULL; acc[j][1] = 0ULL; }
        #pragma unroll 1
        for (int ic = 0; ic < 4; ic++) {
            #pragma unroll
            for (int ky = 0; ky < 8; ky++) {
                const float4* ip = (const float4*)&sI[ic*4464 + (4*oyL+ky)*124 + 8*oxp];
                float4 i0 = ip[0], i1 = ip[1], i2 = ip[2];
                float inr[12] = {i0.x,i0.y,i0.z,i0.w, i1.x,i1.y,i1.z,i1.w, i2.x,i2.y,i2.z,i2.w};
                #pragma unroll
                for (int kx = 0; kx < 8; kx++) {
                    int k = ic*64 + ky*8 + kx;
                    const ulonglong2* wp = (const ulonglong2*)&sW[k*36 + och*8];
                    ulonglong2 wa = wp[0], wb = wp[1];
                    ULL d0 = dup2(inr[kx]), d1 = dup2(inr[kx+4]);
                    FMA8(wa, wb, d0, d1, acc);
                }
            }
        }
        int oy = 8*p + oyL;
        if (act && oy < 30) {
            float* op = g_x1 + (size_t)n*28800 + oy*30 + 2*oxp;
            #pragma unroll
            for (int j = 0; j < 4; j++) {
                int oc = och*8 + 2*j;
                float2 a0 = unpack2(acc[j][0]), a1 = unpack2(acc[j][1]);
                float b0 = bias[oc], b1 = bias[oc+1];
                float2 v0 = make_float2(fmaxf(a0.x*inv255 + b0, 0.f), fmaxf(a1.x*inv255 + b0, 0.f));
                float2 v1 = make_float2(fmaxf(a0.y*inv255 + b1, 0.f), fmaxf(a1.y*inv255 + b1, 0.f));
                *(float2*)&op[(size_t)oc*900]     = v0;
                *(float2*)&op[(size_t)(oc+1)*900] = v1;
            }
        }
    }
}

// ---------------- conv2: [512,32,30,30] -> [512,64,14,14], 4x4 s2 ----------------
// grid (512, 2). 448 thr = 2 ksplit x 2 ocg(16 oc) x 112 spatial. in-block ic-split.
__global__ __launch_bounds__(448, 1)
void k_conv2(const float* __restrict__ w, const float* __restrict__ bias) {
    extern __shared__ float s2[];
    float* sW = s2;            // [k 512][oc pad 36] = 18432
    float* sI = s2 + 18432;    // [ic 32][y 30][x pad 32] = 30720
    int n = blockIdx.x, h = blockIdx.y, tid = threadIdx.x;
    for (int i = tid; i < 16384; i += 448) {
        int oc = i >> 9, k = i & 511;
        sW[k*36 + oc] = w[(h*32+oc)*512 + k];
    }
    const float* src = g_x1 + (size_t)n*28800;
    for (int i = tid; i < 28800; i += 448) {
        int ic = i / 900, r = i - ic*900;
        int y = r / 30, x = r - y*30;
        sI[ic*960 + y*32 + x] = src[i];
    }
    __syncthreads();
    int ks = tid / 224, r = tid - ks*224;
    int ocg = r / 112, idx = r - ocg*112;
    bool act = idx < 98;
    int oy = act ? idx/7 : 0, oxp = act ? idx%7 : 0;
    ULL acc[8][2];
    #pragma unroll
    for (int j = 0; j < 8; j++) { acc[j][0] = 0ULL; acc[j][1] = 0ULL; }
    #pragma unroll 1
    for (int ic = ks*16; ic < ks*16 + 16; ic++) {
        #pragma unroll
        for (int ky = 0; ky < 4; ky++) {
            const float4* ip = (const float4*)&sI[ic*960 + (2*oy+ky)*32 + 4*oxp];
            float4 i0 = ip[0], i1 = ip[1];
            float inr[8] = {i0.x,i0.y,i0.z,i0.w, i1.x,i1.y,i1.z,i1.w};
            #pragma unroll
            for (int kx = 0; kx < 4; kx++) {
                int k = ic*16 + ky*4 + kx;
                const ulonglong2* wp = (const ulonglong2*)&sW[k*36 + ocg*16];
                ulonglong2 wa = wp[0], wb = wp[1], wc = wp[2], wd = wp[3];
                ULL d0 = dup2(inr[kx]), d1 = dup2(inr[kx+2]);
                FMA16(wa, wb, wc, wd, d0, d1, acc);
            }
        }
    }
    __syncthreads();
    ULL* buf = (ULL*)sW;                 // 224*16 ULL = 28672 B < 73728 B
    if (ks == 1) {
        #pragma unroll
        for (int j = 0; j < 8; j++) {
            buf[r*16 + 2*j]     = acc[j][0];
            buf[r*16 + 2*j + 1] = acc[j][1];
        }
    }
    __syncthreads();
    if (ks == 0 && act) {
        float* op = g_x2 + (size_t)(n*64 + h*32)*196 + oy*14 + 2*oxp;
        #pragma unroll
        for (int j = 0; j < 8; j++) {
            ULL s0 = add2(acc[j][0], buf[r*16 + 2*j]);
            ULL s1 = add2(acc[j][1], buf[r*16 + 2*j + 1]);
            int oc = ocg*16 + 2*j;
            float2 a0 = unpack2(s0), a1 = unpack2(s1);
            float b0 = bias[h*32 + oc], b1 = bias[h*32 + oc + 1];
            float2 v0 = make_float2(fmaxf(a0.x + b0, 0.f), fmaxf(a1.x + b0, 0.f));
            float2 v1 = make_float2(fmaxf(a0.y + b1, 0.f), fmaxf(a1.y + b1, 0.f));
            *(float2*)&op[(size_t)oc*196]     = v0;
            *(float2*)&op[(size_t)(oc+1)*196] = v1;
        }
    }
}

// ---------------- conv3: [512,64,14,14] -> [512,32,12,12], 3x3 s1 ----------------
// grid 256 (2 imgs/block). 576 thr = 2 ksplit x (2 img x 2 ocg(16 oc) x 72 spatial).
__global__ __launch_bounds__(576, 1)
void k_conv3(const float* __restrict__ w, const float* __restrict__ bias) {
    extern __shared__ float s3[];
    float* sW = s3;            // [k 576][oc pad 36] = 20736
    float* sI = s3 + 20736;    // [img 2][ic 64][y 14][x pad 16] = 28672
    int n0 = blockIdx.x*2, tid = threadIdx.x;
    for (int i = tid; i < 18432; i += 576) {
        int oc = i / 576, k = i - oc*576;
        sW[k*36 + oc] = w[i];
    }
    for (int i = tid; i < 25088; i += 576) {
        int img = i / 12544, r = i - img*12544;
        int ic = r / 196, r2 = r - ic*196;
        int y = r2 / 14, x = r2 - y*14;
        sI[img*14336 + ic*224 + y*16 + x] = g_x2[(size_t)(n0+img)*12544 + r];
    }
    __syncthreads();
    int ks = tid / 288, r = tid - ks*288;
    int img = r / 144, rr = r - img*144;
    int ocg = rr / 72, sp = rr - ocg*72;
    int oy = sp / 6, oxp = sp - oy*6;
    int x0 = 2*oxp, al = x0 & ~3, o = x0 & 3;
    ULL acc[8][2];
    #pragma unroll
    for (int j = 0; j < 8; j++) { acc[j][0] = 0ULL; acc[j][1] = 0ULL; }
    const float* base = sI + img*14336;
    #pragma unroll 1
    for (int ic = ks*32; ic < ks*32 + 32; ic++) {
        #pragma unroll
        for (int ky = 0; ky < 3; ky++) {
            const float4* ip = (const float4*)&base[ic*224 + (oy+ky)*16 + al];
            float4 i0 = ip[0], i1 = ip[1];
            float inr[8] = {i0.x,i0.y,i0.z,i0.w, i1.x,i1.y,i1.z,i1.w};
            #pragma unroll
            for (int kx = 0; kx < 3; kx++) {
                int k = ic*9 + ky*3 + kx;
                const ulonglong2* wp = (const ulonglong2*)&sW[k*36 + ocg*16];
                ulonglong2 wa = wp[0], wb = wp[1], wc = wp[2], wd = wp[3];
                ULL d0 = dup2(inr[o+kx]), d1 = dup2(inr[o+1+kx]);
                FMA16(wa, wb, wc, wd, d0, d1, acc);
            }
        }
    }
    __syncthreads();
    ULL* buf = (ULL*)sW;                 // 288*16 ULL = 36864 B < 82944 B
    if (ks == 1) {
        #pragma unroll
        for (int j = 0; j < 8; j++) {
            buf[r*16 + 2*j]     = acc[j][0];
            buf[r*16 + 2*j + 1] = acc[j][1];
        }
    }
    __syncthreads();
    if (ks == 0) {
        float* op = g_x3 + (size_t)(n0+img)*4608 + oy*12 + 2*oxp;
        #pragma unroll
        for (int j = 0; j < 8; j++) {
            ULL s0 = add2(acc[j][0], buf[r*16 + 2*j]);
            ULL s1 = add2(acc[j][1], buf[r*16 + 2*j + 1]);
            int oc = ocg*16 + 2*j;
            float2 a0 = unpack2(s0), a1 = unpack2(s1);
            float b0 = bias[oc], b1 = bias[oc+1];
            float2 v0 = make_float2(fmaxf(a0.x + b0, 0.f), fmaxf(a1.x + b0, 0.f));
            float2 v1 = make_float2(fmaxf(a0.y + b1, 0.f), fmaxf(a1.y + b1, 0.f));
            *(float2*)&op[(size_t)oc*144]     = v0;
            *(float2*)&op[(size_t)(oc+1)*144] = v1;
        }
    }
}

// ---------------- split-K f32x2 GEMM v3 ----------------
template<int N, int K, int S>
__global__ void k_gemm3(const float* __restrict__ A, const float* __restrict__ Bm,
                        float* __restrict__ Cp) {
    const int KS = K / S;
    __shared__ __align__(16) float As[16*128];   // [k][m] m-transposed
    __shared__ __align__(16) float Bs[16*128];   // [k][n] natural
    int tid = threadIdx.x;
    int tx = tid & 15, ty = tid >> 4;
    int n0 = blockIdx.x*128, m0 = blockIdx.y*128, ks = blockIdx.z;
    int kbase = ks*KS;
    const int MN = gridDim.y*128*N;

    ULL acc[4][8];
    #pragma unroll
    for (int i = 0; i < 4; i++)
        #pragma unroll
        for (int j = 0; j < 8; j++) acc[i][j] = 0ULL;

    int mA = tid & 127, cA = tid >> 7;

    for (int k0 = kbase; k0 < kbase + KS; k0 += 16) {
        __syncthreads();
        #pragma unroll
        for (int u = 0; u < 2; u++) {
            int c = cA + 2*u;
            float4 v = *(const float4*)&A[(size_t)(m0+mA)*K + k0 + 4*c];
            As[(4*c+0)*128 + mA] = v.x;
            As[(4*c+1)*128 + mA] = v.y;
            As[(4*c+2)*128 + mA] = v.z;
            As[(4*c+3)*128 + mA] = v.w;
        }
        #pragma unroll
        for (int u = 0; u < 2; u++) {
            int c = cA + 2*u;
            float4 v = *(const float4*)&Bm[(size_t)(n0+mA)*K + k0 + 4*c];
            Bs[(4*c+0)*128 + mA] = v.x;
            Bs[(4*c+1)*128 + mA] = v.y;
            Bs[(4*c+2)*128 + mA] = v.z;
            Bs[(4*c+3)*128 + mA] = v.w;
        }
        __syncthreads();
        #pragma unroll
        for (int kk = 0; kk < 16; kk++) {
            ulonglong2 aA = *(const ulonglong2*)&As[kk*128 + 8*ty];
            ulonglong2 aB = *(const ulonglong2*)&As[kk*128 + 8*ty + 4];
            float4 b0 = *(const float4*)&Bs[kk*128 + 4*tx];
            float4 b1 = *(const float4*)&Bs[kk*128 + 64 + 4*tx];
            ULL a[4] = {aA.x, aA.y, aB.x, aB.y};
            ULL bd[8] = {dup2(b0.x), dup2(b0.y), dup2(b0.z), dup2(b0.w),
                         dup2(b1.x), dup2(b1.y), dup2(b1.z), dup2(b1.w)};
            #pragma unroll
            for (int i = 0; i < 4; i++)
                #pragma unroll
                for (int j = 0; j < 8; j++)
                    acc[i][j] = ffma2(a[i], bd[j], acc[i][j]);
        }
    }
    float* cp = Cp + (size_t)ks*MN;
    #pragma unroll
    for (int i = 0; i < 4; i++) {
        int m = m0 + 8*ty + 2*i;
        #pragma unroll
        for (int j = 0; j < 8; j++) {
            int nn = n0 + (j < 4 ? 4*tx + j : 64 + 4*tx + (j-4));
            float2 v = unpack2(acc[i][j]);
            cp[(size_t)m*N + nn]     = v.x;
            cp[(size_t)(m+1)*N + nn] = v.y;
        }
    }
}

template<int S, int NC, bool RELU>
__global__ void k_red(const float* __restrict__ bias, float* __restrict__ C, int MN) {
    int i = blockIdx.x*256 + threadIdx.x;
    if (i >= MN) return;
    float s = bias[i % NC];
    #pragma unroll
    for (int j = 0; j < S; j++) s += g_red[(size_t)j*MN + i];
    C[i] = RELU ? fmaxf(s, 0.f) : s;
}

// ---------------- GRU: persistent, 64 blocks, k-split 2 per thread ----------------
__global__ void k_init_h(const float* __restrict__ states) {
    int i = blockIdx.x*256 + threadIdx.x;   // < 8192
    g_h[i] = states[i];
    if (i == 0) g_bar = 0;
}

__global__ void k_gru(const float* __restrict__ w_hh, const float* __restrict__ masks,
                      const float* __restrict__ b_hh) {
    extern __shared__ float sm[];
    float* w_s = sm;                 // 24*512 = 12288
    float* h_s = sm + 12288;         // 16*514 = 8224
    int tid = threadIdx.x, b = blockIdx.x;
    int hh0 = b*8;
    for (int idx = tid; idx < 12288; idx += 256) {
        int lr = idx >> 9, k = idx & 511;
        int grow = (lr >> 3)*512 + hh0 + (lr & 7);
        w_s[idx] = w_hh[(size_t)grow*512 + k];
    }
    int hh_l = tid >> 5, n = (tid >> 1) & 15, ks = tid & 1;
    int hh = hh0 + hh_l;
    float br = b_hh[hh], bz = b_hh[512+hh], bn = b_hh[1024+hh];
    const float* wr = w_s + hh_l*512 + ks*256;
    const float* wz = w_s + (8+hh_l)*512 + ks*256;
    const float* wn = w_s + (16+hh_l)*512 + ks*256;
    const float* hp = h_s + n*514 + ks*256;

    for (int t = 0; t < 32; t++) {
        int row = t*16 + n;
        float gi_r = g_gi[(size_t)row*1536 + hh];
        float gi_z = g_gi[(size_t)row*1536 + 512 + hh];
        float gi_n = g_gi[(size_t)row*1536 + 1024 + hh];
        for (int idx = tid; idx < 8192; idx += 256) {
            int nn = idx >> 9, k = idx & 511;
            h_s[nn*514 + k] = g_h[idx] * masks[t*16 + nn];
        }
        __syncthreads();

        ULL ar0=0,ar1=0, az0=0,az1=0, an0=0,an1=0;
        #pragma unroll 8
        for (int k = 0; k < 256; k += 8) {
            ULL h0 = *(const ULL*)(hp+k);
            ULL h1 = *(const ULL*)(hp+k+2);
            ULL h2 = *(const ULL*)(hp+k+4), h3 = *(const ULL*)(hp+k+6);
            ulonglong2 ra = *(const ulonglong2*)(wr+k), rb = *(const ulonglong2*)(wr+k+4);
            ulonglong2 za = *(const ulonglong2*)(wz+k), zb = *(const ulonglong2*)(wz+k+4);
            ulonglong2 na = *(const ulonglong2*)(wn+k), nb = *(const ulonglong2*)(wn+k+4);
            ar0 = ffma2(ra.x, h0, ar0); ar1 = ffma2(ra.y, h1, ar1);
            az0 = ffma2(za.x, h0, az0); az1 = ffma2(za.y, h1, az1);
            an0 = ffma2(na.x, h0, an0); an1 = ffma2(na.y, h1, an1);
            ar0 = ffma2(rb.x, h2, ar0); ar1 = ffma2(rb.y, h3, ar1);
            az0 = ffma2(zb.x, h2, az0); az1 = ffma2(zb.y, h3, az1);
            an0 = ffma2(nb.x, h2, an0); an1 = ffma2(nb.y, h3, an1);
        }
        float2 u0 = unpack2(ar0), u1 = unpack2(ar1);
        float sr = u0.x + u0.y + u1.x + u1.y;
        u0 = unpack2(az0); u1 = unpack2(az1);
        float sz = u0.x + u0.y + u1.x + u1.y;
        u0 = unpack2(an0); u1 = unpack2(an1);
        float sn = u0.x + u0.y + u1.x + u1.y;
        sr += __shfl_xor_sync(0xffffffffu, sr, 1);
        sz += __shfl_xor_sync(0xffffffffu, sz, 1);
        sn += __shfl_xor_sync(0xffffffffu, sn, 1);
        sr += br; sz += bz; sn += bn;

        float rg = 1.f/(1.f + expf(-(gi_r + sr)));
        float zg = 1.f/(1.f + expf(-(gi_z + sz)));
        float ng = tanhf(gi_n + rg*sn);
        float hm = h_s[n*514 + hh];
        float hnew = (1.f - zg)*ng + zg*hm;
        if (ks == 0) {
            g_h[n*512 + hh] = hnew;
            g_outs[(size_t)row*512 + hh] = hnew;
        }

        __threadfence();
        __syncthreads();
        if (tid == 0) {
            atomicAdd(&g_bar, 1);
            while (atomicAdd(&g_bar, 0) < 64*(t+1)) { }
        }
        __syncthreads();
    }
}

// ---------------- heads ----------------
__global__ void k_heads(const float* __restrict__ aw, const float* __restrict__ ab,
                        const float* __restrict__ cw, const float* __restrict__ cb,
                        const int* __restrict__ action, float* __restrict__ out) {
    int wrp = threadIdx.x >> 5, lane = threadIdx.x & 31;
    int row = blockIdx.x*4 + wrp;
    const float* x = g_outs + (size_t)row*512;
    float p[7];
    #pragma unroll
    for (int j = 0; j < 7; j++) p[j] = 0.f;
    for (int k = lane; k < 512; k += 32) {
        float xv = x[k];
        #pragma unroll
        for (int j = 0; j < 6; j++) p[j] += xv * aw[j*512 + k];
        p[6] += xv * cw[k];
    }
    #pragma unroll
    for (int j = 0; j < 7; j++)
        #pragma unroll
        for (int o = 16; o > 0; o >>= 1) p[j] += __shfl_xor_sync(0xffffffffu, p[j], o);
    if (lane == 0) {
        float l[6];
        #pragma unroll
        for (int j = 0; j < 6; j++) l[j] = p[j] + ab[j];
        float v = p[6] + cb[0];
        float m = l[0];
        #pragma unroll
        for (int j = 1; j < 6; j++) m = fmaxf(m, l[j]);
        float se = 0.f;
        #pragma unroll
        for (int j = 0; j < 6; j++) se += expf(l[j] - m);
        float lse = m + logf(se);
        int a = action[row];
        float alp = 0.f;
        #pragma unroll
        for (int j = 0; j < 6; j++) if (j == a) alp = l[j] - lse;
        float ent = 0.f;
        #pragma unroll
        for (int j = 0; j < 6; j++) { float lp = l[j] - lse; ent -= expf(lp)*lp; }
        out[row] = v;
        out[512 + row] = alp;
        out[1024 + row] = ent;
    }
}

__global__ void k_states_out(float* __restrict__ out) {
    int i = blockIdx.x*256 + threadIdx.x;   // < 8192
    out[1536 + i] = g_h[i];
}

// ---------------- launch ----------------
extern "C" void kernel_launch(void* const* d_in, const int* in_sizes, int n_in,
                              void* d_out, int out_size) {
    const float* inputs   = (const float*)d_in[0];
    const float* states   = (const float*)d_in[1];
    const float* masks    = (const float*)d_in[2];
    const int*   action   = (const int*)d_in[3];
    const float* conv1_w  = (const float*)d_in[4];
    const float* conv1_b  = (const float*)d_in[5];
    const float* conv2_w  = (const float*)d_in[6];
    const float* conv2_b  = (const float*)d_in[7];
    const float* conv3_w  = (const float*)d_in[8];
    const float* conv3_b  = (const float*)d_in[9];
    const float* fc_w     = (const float*)d_in[10];
    const float* fc_b     = (const float*)d_in[11];
    const float* w_ih     = (const float*)d_in[12];
    const float* w_hh     = (const float*)d_in[13];
    const float* b_ih     = (const float*)d_in[14];
    const float* b_hh     = (const float*)d_in[15];
    const float* actor_w  = (const float*)d_in[16];
    const float* actor_b  = (const float*)d_in[17];
    const float* critic_w = (const float*)d_in[18];
    const float* critic_b = (const float*)d_in[19];
    float* out = (float*)d_out;
    (void)in_sizes; (void)n_in; (void)out_size;

    float* d_red;  cudaGetSymbolAddress((void**)&d_red, g_red);
    float* d_x3;   cudaGetSymbolAddress((void**)&d_x3, g_x3);
    float* d_fc;   cudaGetSymbolAddress((void**)&d_fc, g_fc);
    float* d_gi;   cudaGetSymbolAddress((void**)&d_gi, g_gi);

    cudaFuncSetAttribute(k_conv1, cudaFuncAttributeMaxDynamicSharedMemorySize, 108288);
    cudaFuncSetAttribute(k_conv2, cudaFuncAttributeMaxDynamicSharedMemorySize, 196608);
    cudaFuncSetAttribute(k_conv3, cudaFuncAttributeMaxDynamicSharedMemorySize, 197632);
    cudaFuncSetAttribute(k_gru,   cudaFuncAttributeMaxDynamicSharedMemorySize, 82048);

    // order puts the ncu capture slot (#4) on k_conv3; init_h only must precede k_gru
    k_conv1<<<512, 512, 108288>>>(inputs, conv1_w, conv1_b);
    k_conv2<<<dim3(512, 2), 448, 196608>>>(conv2_w, conv2_b);
    k_init_h<<<32, 256>>>(states);
    k_conv3<<<256, 576, 197632>>>(conv3_w, conv3_b);

    // fc: M=512, N=512, K=4608, split 16 -> 256 blocks
    k_gemm3<512, 4608, 16><<<dim3(4, 4, 16), 256>>>(d_x3, fc_w, d_red);
    k_red<16, 512, true><<<1024, 256>>>(fc_b, d_fc, 512*512);
    // gi: M=512, N=1536, K=512, split 4 -> 192 blocks
    k_gemm3<1536, 512, 4><<<dim3(12, 4, 4), 256>>>(d_fc, w_ih, d_red);
    k_red<4, 1536, false><<<3072, 256>>>(b_ih, d_gi, 512*1536);

    k_gru<<<64, 256, 82048>>>(w_hh, masks, b_hh);

    k_heads<<<128, 128>>>(actor_w, actor_b, critic_w, critic_b, action, out);
    k_states_out<<<32, 256>>>(out);
}